// round 2
// baseline (speedup 1.0000x reference)
#include <cuda_runtime.h>

// ============================================================================
// 2-layer LSTM (B=256, T=512, I=64, H=512) + linear head, fp32.
// Single persistent kernel: 128 CTAs x 256 threads, custom grid barrier.
// Per step: gates GEMM (K=576 L0 / K=1024 L1) via packed fma.rn.f32x2,
// CTA-local cell update (each CTA owns all 4 gates for its j-slice).
//
// R1 fix: cross-CTA data (g_H) is re-read at the same addresses every 2 steps
// inside ONE persistent kernel -> per-SM L1 holds stale lines. All reads of
// kernel-written shared state now use __ldcg (L2, coherent). Accurate
// expf/tanhf in the cell update to keep recurrent error at the ulp floor.
// ============================================================================

#define NCTA  128
#define NTHR  256
#define BATCHN 256
#define SEQN   512
#define HIDN   512
#define GATESN 2048

typedef unsigned long long u64;

// ---------------- device scratch (static allocation only) -------------------
__device__ float g_Wt0[576 * 2048];          // [k][g]  k<512: Whh0^T, k>=512: Wih0^T
__device__ float g_Wt1[1024 * 2048];         // [k][g]  k<512: Wih1^T, k>=512: Whh1^T
__device__ float g_XT[512 * 64 * 256];       // [t][i][b]
__device__ float g_H[2 * 1024 * 256];        // double-buffered [buf][row][b]; rows 0-511 h0, 512-1023 h1
__device__ float g_C[2 * 512 * 256];         // [layer][j][b]
__device__ float g_b0[2048];
__device__ float g_b1[2048];
__device__ unsigned g_barCnt;
__device__ volatile unsigned g_barGen;

// ---------------- helpers ---------------------------------------------------
__device__ __forceinline__ void grid_barrier() {
    __syncthreads();
    if (threadIdx.x == 0) {
        unsigned gen = g_barGen;
        __threadfence();
        if (atomicAdd(&g_barCnt, 1u) == NCTA - 1u) {
            g_barCnt = 0u;
            __threadfence();
            g_barGen = gen + 1u;
        } else {
            while (g_barGen == gen) { __nanosleep(40); }
        }
        __threadfence();
    }
    __syncthreads();
}

__device__ __forceinline__ float sigm(float x) { return 1.0f / (1.0f + expf(-x)); }

__device__ __forceinline__ void ffma2(u64 &d, u64 a, u64 b) {
    asm("fma.rn.f32x2 %0, %1, %2, %0;" : "+l"(d) : "l"(a), "l"(b));
}
__device__ __forceinline__ u64 rep2(float x) {
    u64 r; asm("mov.b64 %0, {%1, %1};" : "=l"(r) : "f"(x)); return r;
}
__device__ __forceinline__ void unpk(u64 v, float &lo, float &hi) {
    asm("mov.b64 {%0, %1}, %2;" : "=f"(lo), "=f"(hi) : "l"(v));
}

// ---------------- one (layer, timestep) phase -------------------------------
// CTA computes gates for 64 gate-rows (4 gates x 16 j) x 64 batches, then the
// LSTM cell update for its (j, b) tile. K rows [0,512) come from srcA,
// rows [512, nkt*32) from srcB.
__device__ __forceinline__ void lstm_phase(
    const float* __restrict__ Wt, int nkt,
    const float* __restrict__ srcA, const float* __restrict__ srcB,
    const float* __restrict__ bias,
    float* __restrict__ Cst, float* __restrict__ Hdst,
    int j0, int b0, float* sW, float* sH)
{
    const int tid = threadIdx.x;
    const int tx = tid & 15;   // batch quad:  b = b0 + tx*4 .. +3
    const int ty = tid >> 4;   // gate  quad:  cols ty*4 .. +3 of the 64-col tile

    // per-thread cooperative-load geometry (tile = 32 k-rows x 64 cols)
    int kkv[8], wcol[8], hoff[8];
#pragma unroll
    for (int e = 0; e < 8; e++) {
        int idx = e * NTHR + tid;
        int kk = idx >> 6, q = idx & 63;
        kkv[e]  = kk;
        wcol[e] = ((q >> 4) << 9) + j0 + (q & 15);   // gate-block * 512 + j
        hoff[e] = kk * BATCHN + b0 + q;
    }

    float rw[8], rh[8];
    {   // preload tile 0 (always srcA).  srcA/srcB are kernel-written
        // cross-CTA state -> MUST bypass L1 (__ldcg) for coherence.
#pragma unroll
        for (int e = 0; e < 8; e++) {
            rw[e] = __ldg(Wt + kkv[e] * GATESN + wcol[e]);
            rh[e] = __ldcg(srcA + hoff[e]);
        }
    }

    u64 acc[4][2];
#pragma unroll
    for (int gi = 0; gi < 4; gi++) { acc[gi][0] = 0ull; acc[gi][1] = 0ull; }

    for (int kt = 0; kt < nkt; kt++) {
        float* bW = sW + (kt & 1) * 2048;
        float* bH = sH + (kt & 1) * 2048;
#pragma unroll
        for (int e = 0; e < 8; e++) {
            int idx = e * NTHR + tid;
            bW[idx] = rw[e];
            bH[idx] = rh[e];
        }
        __syncthreads();
        if (kt + 1 < nkt) {   // prefetch next tile into registers
            int kn = kt + 1;
            const float* hb = (kn < 16) ? (srcA + kn * 32 * BATCHN)
                                        : (srcB + (kn - 16) * 32 * BATCHN);
            const float* wb = Wt + kn * 32 * GATESN;
#pragma unroll
            for (int e = 0; e < 8; e++) {
                rw[e] = __ldg(wb + kkv[e] * GATESN + wcol[e]);
                rh[e] = __ldcg(hb + hoff[e]);
            }
        }
        // compute 32 k-steps from smem (packed f32x2 FMAs, b-paired)
#pragma unroll
        for (int kk = 0; kk < 32; kk++) {
            const float4 wv = *reinterpret_cast<const float4*>(bW + kk * 64 + (ty << 2));
            const u64* hp  = reinterpret_cast<const u64*>(bH + kk * 64 + (tx << 2));
            u64 h0 = hp[0], h1 = hp[1];
            u64 w;
            w = rep2(wv.x); ffma2(acc[0][0], w, h0); ffma2(acc[0][1], w, h1);
            w = rep2(wv.y); ffma2(acc[1][0], w, h0); ffma2(acc[1][1], w, h1);
            w = rep2(wv.z); ffma2(acc[2][0], w, h0); ffma2(acc[2][1], w, h1);
            w = rep2(wv.w); ffma2(acc[3][0], w, h0); ffma2(acc[3][1], w, h1);
        }
    }
    __syncthreads();

    // stage gates (+bias) into smem: gsm[col][b_local], col 0-15=i,16-31=f,32-47=g,48-63=o
    float* gsm = sW;
#pragma unroll
    for (int gi = 0; gi < 4; gi++) {
        int col  = (ty << 2) + gi;
        int gcol = ((col >> 4) << 9) + j0 + (col & 15);
        float bv = __ldg(bias + gcol);
        float lo, hi;
        unpk(acc[gi][0], lo, hi);
        gsm[col * 64 + (tx << 2) + 0] = lo + bv;
        gsm[col * 64 + (tx << 2) + 1] = hi + bv;
        unpk(acc[gi][1], lo, hi);
        gsm[col * 64 + (tx << 2) + 2] = lo + bv;
        gsm[col * 64 + (tx << 2) + 3] = hi + bv;
    }
    __syncthreads();

    // cell update: 16 j x 64 b = 1024 cells, 4 per thread.
    // C is CTA-private (same SM writes & reads) -> plain loads are coherent.
#pragma unroll
    for (int e = 0; e < 4; e++) {
        int cell = tid + e * NTHR;
        int jl = cell >> 6, bl = cell & 63;
        float iv = gsm[jl * 64 + bl];
        float fv = gsm[(16 + jl) * 64 + bl];
        float gv = gsm[(32 + jl) * 64 + bl];
        float ov = gsm[(48 + jl) * 64 + bl];
        int off = (j0 + jl) * BATCHN + b0 + bl;
        float c = Cst[off];
        c = sigm(fv) * c + sigm(iv) * tanhf(gv);
        Cst[off]  = c;
        Hdst[off] = sigm(ov) * tanhf(c);
    }
    __syncthreads();
}

// ---------------- the persistent kernel -------------------------------------
__global__ void __launch_bounds__(NTHR, 1) lstm_all(
    const float* __restrict__ x,
    const float* __restrict__ Wih0, const float* __restrict__ Whh0,
    const float* __restrict__ bih0, const float* __restrict__ bhh0,
    const float* __restrict__ Wih1, const float* __restrict__ Whh1,
    const float* __restrict__ bih1, const float* __restrict__ bhh1,
    const float* __restrict__ Wout, const float* __restrict__ bout,
    float* __restrict__ out)
{
    __shared__ __align__(16) float sW[2 * 2048];
    __shared__ __align__(16) float sH[2 * 2048];
    const int tid  = threadIdx.x;
    const int gtid = blockIdx.x * NTHR + tid;
    const int NT   = NCTA * NTHR;

    // ---- phase 0: transposes, bias folding, state init ----
    for (int i = gtid; i < 576 * 2048; i += NT) {
        int k = i >> 11, g = i & 2047;
        g_Wt0[i] = (k < 512) ? Whh0[g * 512 + k] : Wih0[g * 64 + (k - 512)];
    }
    for (int i = gtid; i < 1024 * 2048; i += NT) {
        int k = i >> 11, g = i & 2047;
        g_Wt1[i] = (k < 512) ? Wih1[g * 512 + k] : Whh1[g * 512 + (k - 512)];
    }
    for (int i = gtid; i < 512 * 64 * 256; i += NT) {
        int t = i >> 14, r = i & 16383, ii = r >> 8, b = r & 255;
        g_XT[i] = x[((b << 9) + t) * 64 + ii];
    }
    for (int i = gtid; i < 2048; i += NT) {
        g_b0[i] = bih0[i] + bhh0[i];
        g_b1[i] = bih1[i] + bhh1[i];
    }
    for (int i = gtid; i < 2 * 1024 * 256; i += NT) g_H[i] = 0.f;
    for (int i = gtid; i < 2 * 512 * 256;  i += NT) g_C[i] = 0.f;

    grid_barrier();

    const int j0 = (blockIdx.x >> 2) * 16;   // 32 j-tiles
    const int b0 = (blockIdx.x & 3) * 64;    // 4 batch-tiles

    for (int t = 0; t < SEQN; t++) {
        int ri = t & 1, wi = ri ^ 1;
        // layer 0: K = 512 (h0 prev) + 64 (x_t)
        lstm_phase(g_Wt0, 18,
                   g_H + ri * 262144,           // h0(t-1), rows 0-511
                   g_XT + t * 16384,            // x_t as [i][b]
                   g_b0, g_C, g_H + wi * 262144,
                   j0, b0, sW, sH);
        grid_barrier();
        // layer 1: K = 512 (h0 current) + 512 (h1 prev)
        lstm_phase(g_Wt1, 32,
                   g_H + wi * 262144,            // h0(t), rows 0-511 of write buf
                   g_H + ri * 262144 + 131072,   // h1(t-1)
                   g_b1, g_C + 131072, g_H + wi * 262144 + 131072,
                   j0, b0, sW, sH);
        grid_barrier();
    }

    // ---- head: out[b] = b_out + sum_j relu(h1_last[j][b]) * W_out[j] ----
    // final write buffer: t=511 -> wi = 0.  g_H was written by other CTAs and
    // these addresses were read earlier by this CTA -> __ldcg mandatory.
    if (blockIdx.x == 0) {
        int b = tid;
        float a = __ldg(bout);
        const float* hp = g_H + 131072 + b;   // buf 0, rows 512.., column b
#pragma unroll 8
        for (int j = 0; j < 512; j++)
            a += fmaxf(__ldcg(hp + j * 256), 0.f) * __ldg(Wout + j);
        out[b] = a;
    }
}

// ---------------- launch ----------------------------------------------------
extern "C" void kernel_launch(void* const* d_in, const int* in_sizes, int n_in,
                              void* d_out, int out_size) {
    (void)in_sizes; (void)n_in; (void)out_size;
    const float* x    = (const float*)d_in[0];
    const float* Wih0 = (const float*)d_in[1];
    const float* Whh0 = (const float*)d_in[2];
    const float* bih0 = (const float*)d_in[3];
    const float* bhh0 = (const float*)d_in[4];
    const float* Wih1 = (const float*)d_in[5];
    const float* Whh1 = (const float*)d_in[6];
    const float* bih1 = (const float*)d_in[7];
    const float* bhh1 = (const float*)d_in[8];
    const float* Wout = (const float*)d_in[9];
    const float* bout = (const float*)d_in[10];
    float* out = (float*)d_out;

    lstm_all<<<NCTA, NTHR>>>(x, Wih0, Whh0, bih0, bhh0,
                             Wih1, Whh1, bih1, bhh1, Wout, bout, out);
}

// round 7
// speedup vs baseline: 2.1272x; 2.1272x over previous
#include <cuda_runtime.h>
#include <cuda_bf16.h>

// ============================================================================
// 2-layer LSTM (B=256, T=512, I=64, H=512) + head on sm_100 base via
// mma.sync.m16n8k16 bf16, 3-term split precision (Whi*hhi + Whi*hlo + Wlo*hhi),
// fp32 accum. 128 persistent CTAs x 256 thr, grid barrier per (step, layer).
// Operands pre-packed in gmem in HMMA fragment order -> mainloop is pure
// LDG.128 + HMMA, no smem staging. h exchanged via gmem: STG writers,
// __ldcg readers (L1-coherence rule from R1).
// R6 fix: B block pointers were missing the per-lane offset (+lane) -- every
// lane loaded lane 0's fragment. A had +lane*2; B now has +lane.
// ============================================================================

typedef unsigned u32;

#define NCTA 128
#define NTHR 256
#define NQ0  36     // layer-0 k16 tiles: 32 (h0) + 4 (x)
#define NQ1  64     // layer-1 k16 tiles: 32 (h0 cur) + 32 (h1 prev)

// ---------------- device scratch (static) -----------------------------------
// A blocks: 1KB per (mt, q): lane 32B = [a0..a3 hi | a0..a3 lo]
__device__ __align__(16) __nv_bfloat16 g_WP0[128 * NQ0 * 512];
__device__ __align__(16) __nv_bfloat16 g_WP1[128 * NQ1 * 512];
// B blocks: 512B per (t/q', n8): lane 16B = [b0 hi, b1 hi, b0 lo, b1 lo]
__device__ __align__(16) __nv_bfloat16 g_XP[512 * 4 * 32 * 256];
// h blocks: [parity][layer][q 0..31][n8 0..31] 512B blocks
__device__ __align__(16) __nv_bfloat16 g_HB[2 * 2 * 32 * 32 * 256];
__device__ float g_C[2 * 512 * 256];
__device__ float g_h1fin[512 * 256];
__device__ float g_bias[2 * 2048];
__device__ u32 g_barCnt;
__device__ volatile u32 g_barGen;

// ---------------- helpers ---------------------------------------------------
__device__ __forceinline__ void grid_barrier() {
    __syncthreads();
    if (threadIdx.x == 0) {
        u32 gen = g_barGen;
        __threadfence();
        if (atomicAdd(&g_barCnt, 1u) == NCTA - 1u) {
            g_barCnt = 0u;
            __threadfence();
            g_barGen = gen + 1u;
        } else {
            while (g_barGen == gen) { __nanosleep(40); }
        }
        __threadfence();
    }
    __syncthreads();
}

__device__ __forceinline__ float sigm(float x) { return 1.0f / (1.0f + expf(-x)); }

__device__ __forceinline__ void mma4(float* d, uint4 a, u32 b0, u32 b1) {
    asm volatile(
        "mma.sync.aligned.m16n8k16.row.col.f32.bf16.bf16.f32 "
        "{%0,%1,%2,%3}, {%4,%5,%6,%7}, {%8,%9}, {%0,%1,%2,%3};"
        : "+f"(d[0]), "+f"(d[1]), "+f"(d[2]), "+f"(d[3])
        : "r"(a.x), "r"(a.y), "r"(a.z), "r"(a.w), "r"(b0), "r"(b1));
}

// One contiguous K segment: NQ k16-steps. A0p/A1p: per-warp A block ptrs
// (lane-adjusted, +64 uint4 per q). Bp: lane-adjusted B block ptr (+1024
// uint4 per q; the warp's two n8 blocks are Bp and Bp+32). Unroll 4 -> MLP.
template <int NQ>
__device__ __forceinline__ void gemm_seg(
    const uint4* __restrict__ A0p, const uint4* __restrict__ A1p,
    const uint4* __restrict__ Bp, float acc[2][2][4])
{
#pragma unroll 4
    for (int q = 0; q < NQ; q++) {
        uint4 a0h = __ldg(A0p);     uint4 a0l = __ldg(A0p + 1);
        uint4 a1h = __ldg(A1p);     uint4 a1l = __ldg(A1p + 1);
        uint4 b0  = __ldcg(Bp);     uint4 b1  = __ldcg(Bp + 32);
        // 3-term split x 2m x 2n = 12 HMMA
        mma4(acc[0][0], a0h, b0.x, b0.y);
        mma4(acc[0][0], a0h, b0.z, b0.w);
        mma4(acc[0][0], a0l, b0.x, b0.y);
        mma4(acc[0][1], a0h, b1.x, b1.y);
        mma4(acc[0][1], a0h, b1.z, b1.w);
        mma4(acc[0][1], a0l, b1.x, b1.y);
        mma4(acc[1][0], a1h, b0.x, b0.y);
        mma4(acc[1][0], a1h, b0.z, b0.w);
        mma4(acc[1][0], a1l, b0.x, b0.y);
        mma4(acc[1][1], a1h, b1.x, b1.y);
        mma4(acc[1][1], a1h, b1.z, b1.w);
        mma4(acc[1][1], a1l, b1.x, b1.y);
        A0p += 64; A1p += 64; Bp += 1024;
    }
}

// ---------------- the persistent kernel -------------------------------------
__global__ void __launch_bounds__(NTHR, 1) lstm_all(
    const float* __restrict__ x,
    const float* __restrict__ Wih0, const float* __restrict__ Whh0,
    const float* __restrict__ bih0, const float* __restrict__ bhh0,
    const float* __restrict__ Wih1, const float* __restrict__ Whh1,
    const float* __restrict__ bih1, const float* __restrict__ bhh1,
    const float* __restrict__ Wout, const float* __restrict__ bout,
    float* __restrict__ out)
{
    __shared__ __align__(16) float gsm[64 * 64];   // gate stage, 16KB

    const int tid  = threadIdx.x;
    const int wid  = tid >> 5;
    const int lane = tid & 31;
    const int gtid = blockIdx.x * NTHR + tid;
    const int NT   = NCTA * NTHR;

    // ======== prep: pack W / x into HMMA fragment order, init state ========
    // WP0: block (mt, q), elem: l*16 + sect*8 + r*2 + h
    for (int i = gtid; i < 128 * NQ0 * 512; i += NT) {
        int bi = i >> 9, off = i & 511;
        int l = off >> 4, rem = off & 15;
        int sect = rem >> 3, r = (rem >> 1) & 3, h = rem & 1;
        int mt = bi / NQ0, q = bi % NQ0;
        int lr = (l >> 2) + (r & 1) * 8;
        int c  = (l & 3) * 2 + h + (r >> 1) * 8;
        int R  = mt * 16 + lr;                       // permuted row = j*4+g
        int GR = (R & 3) * 512 + (R >> 2);           // original gate row
        int k  = q * 16 + c;
        float w = (k < 512) ? Whh0[GR * 512 + k] : Wih0[GR * 64 + (k - 512)];
        __nv_bfloat16 hh = __float2bfloat16_rn(w);
        g_WP0[i] = sect ? __float2bfloat16_rn(w - __bfloat162float(hh)) : hh;
    }
    for (int i = gtid; i < 128 * NQ1 * 512; i += NT) {
        int bi = i >> 9, off = i & 511;
        int l = off >> 4, rem = off & 15;
        int sect = rem >> 3, r = (rem >> 1) & 3, h = rem & 1;
        int mt = bi / NQ1, q = bi % NQ1;
        int lr = (l >> 2) + (r & 1) * 8;
        int c  = (l & 3) * 2 + h + (r >> 1) * 8;
        int R  = mt * 16 + lr;
        int GR = (R & 3) * 512 + (R >> 2);
        int k  = q * 16 + c;
        float w = (k < 512) ? Wih1[GR * 512 + k] : Whh1[GR * 512 + (k - 512)];
        __nv_bfloat16 hh = __float2bfloat16_rn(w);
        g_WP1[i] = sect ? __float2bfloat16_rn(w - __bfloat162float(hh)) : hh;
    }
    // XP: block ((t*4 + q')*32 + n8), elem: l*8 + sect*4 + r*2 + h
    for (int i = gtid; i < 512 * 4 * 32 * 256; i += NT) {
        int bi = i >> 8, off = i & 255;
        int l = off >> 3, rem = off & 7;
        int sect = rem >> 2, r = (rem >> 1) & 1, h = rem & 1;
        int n8 = bi & 31, rest = bi >> 5;
        int qp = rest & 3, t = rest >> 2;
        int kl = r * 8 + (l & 3) * 2 + h;
        int nl = l >> 2;
        int b  = n8 * 8 + nl, ii = qp * 16 + kl;
        float v = x[(b * 512 + t) * 64 + ii];
        __nv_bfloat16 hh = __float2bfloat16_rn(v);
        g_XP[i] = sect ? __float2bfloat16_rn(v - __bfloat162float(hh)) : hh;
    }
    for (int i = gtid; i < 2 * 2 * 32 * 32 * 256; i += NT)
        g_HB[i] = __float2bfloat16(0.f);
    for (int i = gtid; i < 2 * 512 * 256; i += NT) g_C[i] = 0.f;
    for (int i = gtid; i < 2048; i += NT) {
        g_bias[i]        = bih0[i] + bhh0[i];
        g_bias[2048 + i] = bih1[i] + bhh1[i];
    }

    grid_barrier();

    // ======== mainloop ========
    const int m_cta = blockIdx.x >> 2;     // 32 m-tiles: j in [m_cta*16, +16)
    const int n_cta = blockIdx.x & 3;      // 4 n-tiles:  b in [n_cta*64, +64)
    const int wm = wid >> 2;               // 2 warp m-slots (m32 each)
    const int wn = wid & 3;                // 4 warp n-slots (n16 each)
    const int mt0 = m_cta * 4 + wm * 2;    // warp covers mt0, mt0+1
    const int n8b = n_cta * 8 + wn * 2;    // warp covers n8b, n8b+1

    const uint4* WP0v = (const uint4*)g_WP0;
    const uint4* WP1v = (const uint4*)g_WP1;
    const uint4* XPv  = (const uint4*)g_XP;
    const uint4* HBv  = (const uint4*)g_HB;

    for (int t = 0; t < 512; t++) {
        const int pw = t & 1, pr = pw ^ 1;
        for (int lay = 0; lay < 2; lay++) {
            float acc[2][2][4] = {};
            if (lay == 0) {
                const uint4* A0 = WP0v + (mt0 * NQ0) * 64 + lane * 2;
                const uint4* A1 = WP0v + ((mt0 + 1) * NQ0) * 64 + lane * 2;
                gemm_seg<32>(A0, A1,
                             HBv + ((pr * 2 + 0) * 1024 + n8b) * 32 + lane, acc);
                gemm_seg<4>(A0 + 32 * 64, A1 + 32 * 64,
                            XPv + (t * 4 * 32 + n8b) * 32 + lane, acc);
            } else {
                const uint4* A0 = WP1v + (mt0 * NQ1) * 64 + lane * 2;
                const uint4* A1 = WP1v + ((mt0 + 1) * NQ1) * 64 + lane * 2;
                gemm_seg<32>(A0, A1,
                             HBv + ((pw * 2 + 0) * 1024 + n8b) * 32 + lane, acc);
                gemm_seg<32>(A0 + 32 * 64, A1 + 32 * 64,
                             HBv + ((pr * 2 + 1) * 1024 + n8b) * 32 + lane, acc);
            }

            // ---- epilogue: D fragments -> gsm[row_local][col_local] ----
            // (safe to store: previous phase ended with barrier after last read)
#pragma unroll
            for (int mi = 0; mi < 2; mi++)
#pragma unroll
                for (int ni = 0; ni < 2; ni++) {
                    int lr = (wm * 2 + mi) * 16 + (lane >> 2);
                    int cl = (wn * 2 + ni) * 8 + (lane & 3) * 2;
                    float* d = acc[mi][ni];
                    *(float2*)&gsm[lr * 64 + cl]       = make_float2(d[0], d[1]);
                    *(float2*)&gsm[(lr + 8) * 64 + cl] = make_float2(d[2], d[3]);
                }
            __syncthreads();

            // ---- cell update: 16 j x 64 b, 4 cells/thread ----
            float* Cp = g_C + lay * 131072;
            const float* bp = g_bias + lay * 2048;
#pragma unroll
            for (int e = 0; e < 4; e++) {
                int cell = e * NTHR + tid;
                int jl = cell >> 6, bl = cell & 63;
                int j = m_cta * 16 + jl;
                int b = n_cta * 64 + bl;
                float iv = gsm[(jl * 4 + 0) * 64 + bl] + __ldg(bp + 0 * 512 + j);
                float fv = gsm[(jl * 4 + 1) * 64 + bl] + __ldg(bp + 1 * 512 + j);
                float gv = gsm[(jl * 4 + 2) * 64 + bl] + __ldg(bp + 2 * 512 + j);
                float ov = gsm[(jl * 4 + 3) * 64 + bl] + __ldg(bp + 3 * 512 + j);
                float c = Cp[j * 256 + b];
                c = sigm(fv) * c + sigm(iv) * tanhf(gv);
                Cp[j * 256 + b] = c;
                float hv = sigm(ov) * tanhf(c);
                // write h fragments (hi/lo) for next consumers
                __nv_bfloat16 hh = __float2bfloat16_rn(hv);
                __nv_bfloat16 hl = __float2bfloat16_rn(hv - __bfloat162float(hh));
                int n8 = n_cta * 8 + (bl >> 3), nl = bl & 7;
                int lane2 = nl * 4 + ((jl & 7) >> 1);
                int r = jl >> 3, hb = jl & 1;
                int blk = ((pw * 2 + lay) * 32 + m_cta) * 32 + n8;
                __nv_bfloat16* p = g_HB + blk * 256 + lane2 * 8 + r * 2 + hb;
                p[0] = hh;
                p[4] = hl;
                if (lay == 1 && t == 511) g_h1fin[j * 256 + b] = hv;
            }
            __syncthreads();
            grid_barrier();
        }
    }

    // ======== head: out[b] = b_out + sum_j relu(h1[j][b]) * W_out[j] ========
    if (blockIdx.x == 0) {
        int b = tid;
        float a = __ldg(bout);
#pragma unroll 8
        for (int j = 0; j < 512; j++)
            a += fmaxf(__ldcg(g_h1fin + j * 256 + b), 0.f) * __ldg(Wout + j);
        out[b] = a;
    }
}

// ---------------- launch ----------------------------------------------------
extern "C" void kernel_launch(void* const* d_in, const int* in_sizes, int n_in,
                              void* d_out, int out_size) {
    (void)in_sizes; (void)n_in; (void)out_size;
    const float* x    = (const float*)d_in[0];
    const float* Wih0 = (const float*)d_in[1];
    const float* Whh0 = (const float*)d_in[2];
    const float* bih0 = (const float*)d_in[3];
    const float* bhh0 = (const float*)d_in[4];
    const float* Wih1 = (const float*)d_in[5];
    const float* Whh1 = (const float*)d_in[6];
    const float* bih1 = (const float*)d_in[7];
    const float* bhh1 = (const float*)d_in[8];
    const float* Wout = (const float*)d_in[9];
    const float* bout = (const float*)d_in[10];
    float* out = (float*)d_out;

    lstm_all<<<NCTA, NTHR>>>(x, Wih0, Whh0, bih0, bhh0,
                             Wih1, Whh1, bih1, bhh1, Wout, bout, out);
}

// round 8
// speedup vs baseline: 2.6310x; 1.2368x over previous
#include <cuda_runtime.h>
#include <cuda_bf16.h>

// ============================================================================
// 2-layer LSTM (B=256, T=512, I=64, H=512) + head on sm_100 base via
// mma.sync.m16n8k16 bf16, 3-term split precision (Whi*hhi + Whi*hlo + Wlo*hhi),
// fp32 accum. 128 persistent CTAs x 256 thr, grid barrier per (step, layer).
// R8: K-split warp groups. Warps 0-3 = lower K half, warps 4-7 = upper K half;
// each group is a 2x2 grid of m32xn32 warp tiles (8 acc chains/warp, 16/SMSP).
// Partial sums in 2 smem buffers, summed in the cell update. L1 traffic/q
// drops 24KB->16KB (dup_A=2, dup_B=2). Gmem layouts identical to R7 winner.
// ============================================================================

typedef unsigned u32;

#define NCTA 128
#define NTHR 256
#define NQ0  36     // layer-0 k16 tiles: 32 (h0) + 4 (x)
#define NQ1  64     // layer-1 k16 tiles: 32 (h0 cur) + 32 (h1 prev)

// ---------------- device scratch (static) -----------------------------------
// A blocks: 1KB per (mt, q): lane 32B = [a0..a3 hi | a0..a3 lo]
__device__ __align__(16) __nv_bfloat16 g_WP0[128 * NQ0 * 512];
__device__ __align__(16) __nv_bfloat16 g_WP1[128 * NQ1 * 512];
// B blocks: 512B per (t/q', n8): lane 16B = [b0 hi, b1 hi, b0 lo, b1 lo]
__device__ __align__(16) __nv_bfloat16 g_XP[512 * 4 * 32 * 256];
// h blocks: [parity][layer][q 0..31][n8 0..31] 512B blocks
__device__ __align__(16) __nv_bfloat16 g_HB[2 * 2 * 32 * 32 * 256];
__device__ float g_C[2 * 512 * 256];
__device__ float g_h1fin[512 * 256];
__device__ float g_bias[2 * 2048];
__device__ u32 g_barCnt;
__device__ volatile u32 g_barGen;

// ---------------- helpers ---------------------------------------------------
__device__ __forceinline__ void grid_barrier() {
    __syncthreads();
    if (threadIdx.x == 0) {
        u32 gen = g_barGen;
        __threadfence();
        if (atomicAdd(&g_barCnt, 1u) == NCTA - 1u) {
            g_barCnt = 0u;
            __threadfence();
            g_barGen = gen + 1u;
        } else {
            while (g_barGen == gen) { __nanosleep(40); }
        }
        __threadfence();
    }
    __syncthreads();
}

__device__ __forceinline__ float sigm(float x) { return 1.0f / (1.0f + expf(-x)); }

__device__ __forceinline__ void mma4(float* d, uint4 a, u32 b0, u32 b1) {
    asm volatile(
        "mma.sync.aligned.m16n8k16.row.col.f32.bf16.bf16.f32 "
        "{%0,%1,%2,%3}, {%4,%5,%6,%7}, {%8,%9}, {%0,%1,%2,%3};"
        : "+f"(d[0]), "+f"(d[1]), "+f"(d[2]), "+f"(d[3])
        : "r"(a.x), "r"(a.y), "r"(a.z), "r"(a.w), "r"(b0), "r"(b1));
}

// One contiguous K segment of NQ k16-steps for an m32 x n32 warp tile.
// A0p/A1p: lane-adjusted A block ptrs for the two m16 tiles (+64 uint4/q).
// Bp: lane-adjusted B ptr; the warp's four n8 blocks are Bp+{0,32,64,96}
// (+1024 uint4 per q). acc[mi][ni][4]. 24 HMMA per q, 8 chains.
template <int NQ>
__device__ __forceinline__ void gemm_seg(
    const uint4* __restrict__ A0p, const uint4* __restrict__ A1p,
    const uint4* __restrict__ Bp, float acc[2][4][4])
{
#pragma unroll 4
    for (int q = 0; q < NQ; q++) {
        uint4 a0h = __ldg(A0p);     uint4 a0l = __ldg(A0p + 1);
        uint4 a1h = __ldg(A1p);     uint4 a1l = __ldg(A1p + 1);
        uint4 b0  = __ldcg(Bp);
        uint4 b1  = __ldcg(Bp + 32);
        uint4 b2  = __ldcg(Bp + 64);
        uint4 b3  = __ldcg(Bp + 96);
        // 3-term split x 2m x 4n = 24 HMMA
        mma4(acc[0][0], a0h, b0.x, b0.y);
        mma4(acc[0][0], a0h, b0.z, b0.w);
        mma4(acc[0][0], a0l, b0.x, b0.y);
        mma4(acc[0][1], a0h, b1.x, b1.y);
        mma4(acc[0][1], a0h, b1.z, b1.w);
        mma4(acc[0][1], a0l, b1.x, b1.y);
        mma4(acc[0][2], a0h, b2.x, b2.y);
        mma4(acc[0][2], a0h, b2.z, b2.w);
        mma4(acc[0][2], a0l, b2.x, b2.y);
        mma4(acc[0][3], a0h, b3.x, b3.y);
        mma4(acc[0][3], a0h, b3.z, b3.w);
        mma4(acc[0][3], a0l, b3.x, b3.y);
        mma4(acc[1][0], a1h, b0.x, b0.y);
        mma4(acc[1][0], a1h, b0.z, b0.w);
        mma4(acc[1][0], a1l, b0.x, b0.y);
        mma4(acc[1][1], a1h, b1.x, b1.y);
        mma4(acc[1][1], a1h, b1.z, b1.w);
        mma4(acc[1][1], a1l, b1.x, b1.y);
        mma4(acc[1][2], a1h, b2.x, b2.y);
        mma4(acc[1][2], a1h, b2.z, b2.w);
        mma4(acc[1][2], a1l, b2.x, b2.y);
        mma4(acc[1][3], a1h, b3.x, b3.y);
        mma4(acc[1][3], a1h, b3.z, b3.w);
        mma4(acc[1][3], a1l, b3.x, b3.y);
        A0p += 64; A1p += 64; Bp += 1024;
    }
}

// ---------------- the persistent kernel -------------------------------------
__global__ void __launch_bounds__(NTHR, 1) lstm_all(
    const float* __restrict__ x,
    const float* __restrict__ Wih0, const float* __restrict__ Whh0,
    const float* __restrict__ bih0, const float* __restrict__ bhh0,
    const float* __restrict__ Wih1, const float* __restrict__ Whh1,
    const float* __restrict__ bih1, const float* __restrict__ bhh1,
    const float* __restrict__ Wout, const float* __restrict__ bout,
    float* __restrict__ out)
{
    __shared__ __align__(16) float gsm[2 * 64 * 64];   // per-K-group partials, 32KB

    const int tid  = threadIdx.x;
    const int wid  = tid >> 5;
    const int lane = tid & 31;
    const int gtid = blockIdx.x * NTHR + tid;
    const int NT   = NCTA * NTHR;

    // ======== prep: pack W / x into HMMA fragment order, init state ========
    // (identical to R7 winner)
    for (int i = gtid; i < 128 * NQ0 * 512; i += NT) {
        int bi = i >> 9, off = i & 511;
        int l = off >> 4, rem = off & 15;
        int sect = rem >> 3, r = (rem >> 1) & 3, h = rem & 1;
        int mt = bi / NQ0, q = bi % NQ0;
        int lr = (l >> 2) + (r & 1) * 8;
        int c  = (l & 3) * 2 + h + (r >> 1) * 8;
        int R  = mt * 16 + lr;                       // permuted row = j*4+g
        int GR = (R & 3) * 512 + (R >> 2);           // original gate row
        int k  = q * 16 + c;
        float w = (k < 512) ? Whh0[GR * 512 + k] : Wih0[GR * 64 + (k - 512)];
        __nv_bfloat16 hh = __float2bfloat16_rn(w);
        g_WP0[i] = sect ? __float2bfloat16_rn(w - __bfloat162float(hh)) : hh;
    }
    for (int i = gtid; i < 128 * NQ1 * 512; i += NT) {
        int bi = i >> 9, off = i & 511;
        int l = off >> 4, rem = off & 15;
        int sect = rem >> 3, r = (rem >> 1) & 3, h = rem & 1;
        int mt = bi / NQ1, q = bi % NQ1;
        int lr = (l >> 2) + (r & 1) * 8;
        int c  = (l & 3) * 2 + h + (r >> 1) * 8;
        int R  = mt * 16 + lr;
        int GR = (R & 3) * 512 + (R >> 2);
        int k  = q * 16 + c;
        float w = (k < 512) ? Wih1[GR * 512 + k] : Whh1[GR * 512 + (k - 512)];
        __nv_bfloat16 hh = __float2bfloat16_rn(w);
        g_WP1[i] = sect ? __float2bfloat16_rn(w - __bfloat162float(hh)) : hh;
    }
    for (int i = gtid; i < 512 * 4 * 32 * 256; i += NT) {
        int bi = i >> 8, off = i & 255;
        int l = off >> 3, rem = off & 7;
        int sect = rem >> 2, r = (rem >> 1) & 1, h = rem & 1;
        int n8 = bi & 31, rest = bi >> 5;
        int qp = rest & 3, t = rest >> 2;
        int kl = r * 8 + (l & 3) * 2 + h;
        int nl = l >> 2;
        int b  = n8 * 8 + nl, ii = qp * 16 + kl;
        float v = x[(b * 512 + t) * 64 + ii];
        __nv_bfloat16 hh = __float2bfloat16_rn(v);
        g_XP[i] = sect ? __float2bfloat16_rn(v - __bfloat162float(hh)) : hh;
    }
    for (int i = gtid; i < 2 * 2 * 32 * 32 * 256; i += NT)
        g_HB[i] = __float2bfloat16(0.f);
    for (int i = gtid; i < 2 * 512 * 256; i += NT) g_C[i] = 0.f;
    for (int i = gtid; i < 2048; i += NT) {
        g_bias[i]        = bih0[i] + bhh0[i];
        g_bias[2048 + i] = bih1[i] + bhh1[i];
    }

    grid_barrier();

    // ======== mainloop ========
    const int m_cta = blockIdx.x >> 2;     // 32 m-tiles: j in [m_cta*16, +16)
    const int n_cta = blockIdx.x & 3;      // 4 n-tiles:  b in [n_cta*64, +64)
    const int grp = wid >> 2;              // K-half group (0: low, 1: high)
    const int wl  = wid & 3;               // warp within group
    const int wm  = wl >> 1;               // 2 m-slots (m32 each)
    const int wn  = wl & 1;                // 2 n-slots (n32 each)
    const int mt0 = m_cta * 4 + wm * 2;    // warp's two m16 tiles: mt0, mt0+1
    const int n8b = n_cta * 8 + wn * 4;    // warp's four n8 blocks: n8b..+3

    const uint4* WP0v = (const uint4*)g_WP0;
    const uint4* WP1v = (const uint4*)g_WP1;
    const uint4* XPv  = (const uint4*)g_XP;
    const uint4* HBv  = (const uint4*)g_HB;
    float* gout = gsm + grp * 4096;

    for (int t = 0; t < 512; t++) {
        const int pw = t & 1, pr = pw ^ 1;
        for (int lay = 0; lay < 2; lay++) {
            float acc[2][4][4] = {};
            if (lay == 0) {
                // K = 36 q: h0(prev) q0..31, x_t q32..35. Split: g0 q0..17, g1 q18..35.
                const uint4* A0 = WP0v + (mt0 * NQ0) * 64 + lane * 2;
                const uint4* A1 = WP0v + ((mt0 + 1) * NQ0) * 64 + lane * 2;
                const uint4* Bh = HBv + ((pr * 2 + 0) * 1024 + n8b) * 32 + lane;
                if (grp == 0) {
                    gemm_seg<18>(A0, A1, Bh, acc);
                } else {
                    gemm_seg<14>(A0 + 18 * 64, A1 + 18 * 64, Bh + 18 * 1024, acc);
                    gemm_seg<4>(A0 + 32 * 64, A1 + 32 * 64,
                                XPv + (t * 4 * 32 + n8b) * 32 + lane, acc);
                }
            } else {
                // K = 64 q: h0(cur) q0..31, h1(prev) q32..63. Split at 32.
                const uint4* A0 = WP1v + (mt0 * NQ1) * 64 + lane * 2;
                const uint4* A1 = WP1v + ((mt0 + 1) * NQ1) * 64 + lane * 2;
                if (grp == 0) {
                    gemm_seg<32>(A0, A1,
                                 HBv + ((pw * 2 + 0) * 1024 + n8b) * 32 + lane, acc);
                } else {
                    gemm_seg<32>(A0 + 32 * 64, A1 + 32 * 64,
                                 HBv + ((pr * 2 + 1) * 1024 + n8b) * 32 + lane, acc);
                }
            }

            // ---- epilogue: partial D fragments -> this group's gsm buffer ----
#pragma unroll
            for (int mi = 0; mi < 2; mi++)
#pragma unroll
                for (int ni = 0; ni < 4; ni++) {
                    int lr = (wm * 2 + mi) * 16 + (lane >> 2);
                    int cl = (wn * 4 + ni) * 8 + (lane & 3) * 2;
                    float* d = acc[mi][ni];
                    *(float2*)&gout[lr * 64 + cl]       = make_float2(d[0], d[1]);
                    *(float2*)&gout[(lr + 8) * 64 + cl] = make_float2(d[2], d[3]);
                }
            __syncthreads();

            // ---- cell update: 16 j x 64 b, 4 cells/thread ----
            float* Cp = g_C + lay * 131072;
            const float* bp = g_bias + lay * 2048;
#pragma unroll
            for (int e = 0; e < 4; e++) {
                int cell = e * NTHR + tid;
                int jl = cell >> 6, bl = cell & 63;
                int j = m_cta * 16 + jl;
                int b = n_cta * 64 + bl;
                float iv = gsm[(jl * 4 + 0) * 64 + bl] + gsm[4096 + (jl * 4 + 0) * 64 + bl]
                         + __ldg(bp + 0 * 512 + j);
                float fv = gsm[(jl * 4 + 1) * 64 + bl] + gsm[4096 + (jl * 4 + 1) * 64 + bl]
                         + __ldg(bp + 1 * 512 + j);
                float gv = gsm[(jl * 4 + 2) * 64 + bl] + gsm[4096 + (jl * 4 + 2) * 64 + bl]
                         + __ldg(bp + 2 * 512 + j);
                float ov = gsm[(jl * 4 + 3) * 64 + bl] + gsm[4096 + (jl * 4 + 3) * 64 + bl]
                         + __ldg(bp + 3 * 512 + j);
                float c = Cp[j * 256 + b];
                c = sigm(fv) * c + sigm(iv) * tanhf(gv);
                Cp[j * 256 + b] = c;
                float hv = sigm(ov) * tanhf(c);
                // write h fragments (hi/lo) for next consumers
                __nv_bfloat16 hh = __float2bfloat16_rn(hv);
                __nv_bfloat16 hl = __float2bfloat16_rn(hv - __bfloat162float(hh));
                int n8 = n_cta * 8 + (bl >> 3), nl = bl & 7;
                int lane2 = nl * 4 + ((jl & 7) >> 1);
                int r = jl >> 3, hb = jl & 1;
                int blk = ((pw * 2 + lay) * 32 + m_cta) * 32 + n8;
                __nv_bfloat16* p = g_HB + blk * 256 + lane2 * 8 + r * 2 + hb;
                p[0] = hh;
                p[4] = hl;
                if (lay == 1 && t == 511) g_h1fin[j * 256 + b] = hv;
            }
            __syncthreads();
            grid_barrier();
        }
    }

    // ======== head: out[b] = b_out + sum_j relu(h1[j][b]) * W_out[j] ========
    if (blockIdx.x == 0) {
        int b = tid;
        float a = __ldg(bout);
#pragma unroll 8
        for (int j = 0; j < 512; j++)
            a += fmaxf(__ldcg(g_h1fin + j * 256 + b), 0.f) * __ldg(Wout + j);
        out[b] = a;
    }
}

// ---------------- launch ----------------------------------------------------
extern "C" void kernel_launch(void* const* d_in, const int* in_sizes, int n_in,
                              void* d_out, int out_size) {
    (void)in_sizes; (void)n_in; (void)out_size;
    const float* x    = (const float*)d_in[0];
    const float* Wih0 = (const float*)d_in[1];
    const float* Whh0 = (const float*)d_in[2];
    const float* bih0 = (const float*)d_in[3];
    const float* bhh0 = (const float*)d_in[4];
    const float* Wih1 = (const float*)d_in[5];
    const float* Whh1 = (const float*)d_in[6];
    const float* bih1 = (const float*)d_in[7];
    const float* bhh1 = (const float*)d_in[8];
    const float* Wout = (const float*)d_in[9];
    const float* bout = (const float*)d_in[10];
    float* out = (float*)d_out;

    lstm_all<<<NCTA, NTHR>>>(x, Wih0, Whh0, bih0, bhh0,
                             Wih1, Whh1, bih1, bhh1, Wout, bout, out);
}

// round 10
// speedup vs baseline: 3.0561x; 1.1616x over previous
#include <cuda_runtime.h>
#include <cuda_bf16.h>

// ============================================================================
// 2-layer LSTM (B=256, T=512, I=64, H=512) + head on sm_100 base via
// mma.sync.m16n8k16 bf16, 3-term split precision, fp32 accum.
// 128 persistent CTAs x 256 thr.
// R9: merged phases. L1(t-1) and L0(t) are mutually independent, so each
// phase computes BOTH (single grid barrier per phase: 513 instead of 1024).
// Outputs land in two smem regions (64KB dynamic); one combined cell-update
// tail. K-split warp groups (R8) retained: 2 groups x (2x2 warps, m32xn32).
// Barrier spin no longer uses __nanosleep (faster wake).
// ============================================================================

typedef unsigned u32;

#define NCTA 128
#define NTHR 256
#define NQ0  36     // layer-0 k16 tiles: 32 (h0) + 4 (x)
#define NQ1  64     // layer-1 k16 tiles: 32 (h0 cur) + 32 (h1 prev)
#define SMEM_DYN (16384 * 4)   // 2 outputs x 2 K-groups x 64x64 fp32

// ---------------- device scratch (static) -----------------------------------
__device__ __align__(16) __nv_bfloat16 g_WP0[128 * NQ0 * 512];
__device__ __align__(16) __nv_bfloat16 g_WP1[128 * NQ1 * 512];
__device__ __align__(16) __nv_bfloat16 g_XP[512 * 4 * 32 * 256];
__device__ __align__(16) __nv_bfloat16 g_HB[2 * 2 * 32 * 32 * 256];
__device__ float g_C[2 * 512 * 256];
__device__ float g_h1fin[512 * 256];
__device__ float g_bias[2 * 2048];
__device__ u32 g_barCnt;
__device__ volatile u32 g_barGen;

// ---------------- helpers ---------------------------------------------------
__device__ __forceinline__ void grid_barrier() {
    __syncthreads();
    if (threadIdx.x == 0) {
        u32 gen = g_barGen;
        __threadfence();
        if (atomicAdd(&g_barCnt, 1u) == NCTA - 1u) {
            g_barCnt = 0u;
            __threadfence();
            g_barGen = gen + 1u;
        } else {
            while (g_barGen == gen) { }
        }
        __threadfence();
    }
    __syncthreads();
}

__device__ __forceinline__ float sigm(float x) { return 1.0f / (1.0f + expf(-x)); }

__device__ __forceinline__ void mma4(float* d, uint4 a, u32 b0, u32 b1) {
    asm volatile(
        "mma.sync.aligned.m16n8k16.row.col.f32.bf16.bf16.f32 "
        "{%0,%1,%2,%3}, {%4,%5,%6,%7}, {%8,%9}, {%0,%1,%2,%3};"
        : "+f"(d[0]), "+f"(d[1]), "+f"(d[2]), "+f"(d[3])
        : "r"(a.x), "r"(a.y), "r"(a.z), "r"(a.w), "r"(b0), "r"(b1));
}

// One contiguous K segment of NQ k16-steps for an m32 x n32 warp tile.
template <int NQ>
__device__ __forceinline__ void gemm_seg(
    const uint4* __restrict__ A0p, const uint4* __restrict__ A1p,
    const uint4* __restrict__ Bp, float acc[2][4][4])
{
#pragma unroll 4
    for (int q = 0; q < NQ; q++) {
        uint4 a0h = __ldg(A0p);     uint4 a0l = __ldg(A0p + 1);
        uint4 a1h = __ldg(A1p);     uint4 a1l = __ldg(A1p + 1);
        uint4 b0  = __ldcg(Bp);
        uint4 b1  = __ldcg(Bp + 32);
        uint4 b2  = __ldcg(Bp + 64);
        uint4 b3  = __ldcg(Bp + 96);
        mma4(acc[0][0], a0h, b0.x, b0.y);
        mma4(acc[0][0], a0h, b0.z, b0.w);
        mma4(acc[0][0], a0l, b0.x, b0.y);
        mma4(acc[0][1], a0h, b1.x, b1.y);
        mma4(acc[0][1], a0h, b1.z, b1.w);
        mma4(acc[0][1], a0l, b1.x, b1.y);
        mma4(acc[0][2], a0h, b2.x, b2.y);
        mma4(acc[0][2], a0h, b2.z, b2.w);
        mma4(acc[0][2], a0l, b2.x, b2.y);
        mma4(acc[0][3], a0h, b3.x, b3.y);
        mma4(acc[0][3], a0h, b3.z, b3.w);
        mma4(acc[0][3], a0l, b3.x, b3.y);
        mma4(acc[1][0], a1h, b0.x, b0.y);
        mma4(acc[1][0], a1h, b0.z, b0.w);
        mma4(acc[1][0], a1l, b0.x, b0.y);
        mma4(acc[1][1], a1h, b1.x, b1.y);
        mma4(acc[1][1], a1h, b1.z, b1.w);
        mma4(acc[1][1], a1l, b1.x, b1.y);
        mma4(acc[1][2], a1h, b2.x, b2.y);
        mma4(acc[1][2], a1h, b2.z, b2.w);
        mma4(acc[1][2], a1l, b2.x, b2.y);
        mma4(acc[1][3], a1h, b3.x, b3.y);
        mma4(acc[1][3], a1h, b3.z, b3.w);
        mma4(acc[1][3], a1l, b3.x, b3.y);
        A0p += 64; A1p += 64; Bp += 1024;
    }
}

// Store one warp's partial D tile into a gsm region.
__device__ __forceinline__ void store_partials(
    float acc[2][4][4], float* gout, int wm, int wn, int lane)
{
#pragma unroll
    for (int mi = 0; mi < 2; mi++)
#pragma unroll
        for (int ni = 0; ni < 4; ni++) {
            int lr = (wm * 2 + mi) * 16 + (lane >> 2);
            int cl = (wn * 4 + ni) * 8 + (lane & 3) * 2;
            float* d = acc[mi][ni];
            *(float2*)&gout[lr * 64 + cl]       = make_float2(d[0], d[1]);
            *(float2*)&gout[(lr + 8) * 64 + cl] = make_float2(d[2], d[3]);
        }
}

// Cell update for one layer from a gsm output region (two K-group partials).
__device__ __forceinline__ void cell_upd(
    const float* gbase, int lay, int pwv, int m_cta, int n_cta,
    int tid, bool fin)
{
    float* Cp = g_C + lay * 131072;
    const float* bp = g_bias + lay * 2048;
#pragma unroll
    for (int e = 0; e < 4; e++) {
        int cell = e * NTHR + tid;
        int jl = cell >> 6, bl = cell & 63;
        int j = m_cta * 16 + jl;
        int b = n_cta * 64 + bl;
        float iv = gbase[(jl * 4 + 0) * 64 + bl] + gbase[4096 + (jl * 4 + 0) * 64 + bl]
                 + __ldg(bp + 0 * 512 + j);
        float fv = gbase[(jl * 4 + 1) * 64 + bl] + gbase[4096 + (jl * 4 + 1) * 64 + bl]
                 + __ldg(bp + 1 * 512 + j);
        float gv = gbase[(jl * 4 + 2) * 64 + bl] + gbase[4096 + (jl * 4 + 2) * 64 + bl]
                 + __ldg(bp + 2 * 512 + j);
        float ov = gbase[(jl * 4 + 3) * 64 + bl] + gbase[4096 + (jl * 4 + 3) * 64 + bl]
                 + __ldg(bp + 3 * 512 + j);
        float c = Cp[j * 256 + b];
        c = sigm(fv) * c + sigm(iv) * tanhf(gv);
        Cp[j * 256 + b] = c;
        float hv = sigm(ov) * tanhf(c);
        __nv_bfloat16 hh = __float2bfloat16_rn(hv);
        __nv_bfloat16 hl = __float2bfloat16_rn(hv - __bfloat162float(hh));
        int n8 = n_cta * 8 + (bl >> 3), nl = bl & 7;
        int lane2 = nl * 4 + ((jl & 7) >> 1);
        int r = jl >> 3, hb = jl & 1;
        int blk = ((pwv * 2 + lay) * 32 + m_cta) * 32 + n8;
        __nv_bfloat16* p = g_HB + blk * 256 + lane2 * 8 + r * 2 + hb;
        p[0] = hh;
        p[4] = hl;
        if (fin) g_h1fin[j * 256 + b] = hv;
    }
}

// ---------------- the persistent kernel -------------------------------------
extern __shared__ __align__(16) float gsm[];   // [out][grp][64*64] = 16384 floats

__global__ void __launch_bounds__(NTHR, 1) lstm_all(
    const float* __restrict__ x,
    const float* __restrict__ Wih0, const float* __restrict__ Whh0,
    const float* __restrict__ bih0, const float* __restrict__ bhh0,
    const float* __restrict__ Wih1, const float* __restrict__ Whh1,
    const float* __restrict__ bih1, const float* __restrict__ bhh1,
    const float* __restrict__ Wout, const float* __restrict__ bout,
    float* __restrict__ out)
{
    const int tid  = threadIdx.x;
    const int wid  = tid >> 5;
    const int lane = tid & 31;
    const int gtid = blockIdx.x * NTHR + tid;
    const int NT   = NCTA * NTHR;

    // ======== prep: identical to R8 winner ========
    for (int i = gtid; i < 128 * NQ0 * 512; i += NT) {
        int bi = i >> 9, off = i & 511;
        int l = off >> 4, rem = off & 15;
        int sect = rem >> 3, r = (rem >> 1) & 3, h = rem & 1;
        int mt = bi / NQ0, q = bi % NQ0;
        int lr = (l >> 2) + (r & 1) * 8;
        int c  = (l & 3) * 2 + h + (r >> 1) * 8;
        int R  = mt * 16 + lr;
        int GR = (R & 3) * 512 + (R >> 2);
        int k  = q * 16 + c;
        float w = (k < 512) ? Whh0[GR * 512 + k] : Wih0[GR * 64 + (k - 512)];
        __nv_bfloat16 hh = __float2bfloat16_rn(w);
        g_WP0[i] = sect ? __float2bfloat16_rn(w - __bfloat162float(hh)) : hh;
    }
    for (int i = gtid; i < 128 * NQ1 * 512; i += NT) {
        int bi = i >> 9, off = i & 511;
        int l = off >> 4, rem = off & 15;
        int sect = rem >> 3, r = (rem >> 1) & 3, h = rem & 1;
        int mt = bi / NQ1, q = bi % NQ1;
        int lr = (l >> 2) + (r & 1) * 8;
        int c  = (l & 3) * 2 + h + (r >> 1) * 8;
        int R  = mt * 16 + lr;
        int GR = (R & 3) * 512 + (R >> 2);
        int k  = q * 16 + c;
        float w = (k < 512) ? Wih1[GR * 512 + k] : Whh1[GR * 512 + (k - 512)];
        __nv_bfloat16 hh = __float2bfloat16_rn(w);
        g_WP1[i] = sect ? __float2bfloat16_rn(w - __bfloat162float(hh)) : hh;
    }
    for (int i = gtid; i < 512 * 4 * 32 * 256; i += NT) {
        int bi = i >> 8, off = i & 255;
        int l = off >> 3, rem = off & 7;
        int sect = rem >> 2, r = (rem >> 1) & 1, h = rem & 1;
        int n8 = bi & 31, rest = bi >> 5;
        int qp = rest & 3, t = rest >> 2;
        int kl = r * 8 + (l & 3) * 2 + h;
        int nl = l >> 2;
        int b  = n8 * 8 + nl, ii = qp * 16 + kl;
        float v = x[(b * 512 + t) * 64 + ii];
        __nv_bfloat16 hh = __float2bfloat16_rn(v);
        g_XP[i] = sect ? __float2bfloat16_rn(v - __bfloat162float(hh)) : hh;
    }
    for (int i = gtid; i < 2 * 2 * 32 * 32 * 256; i += NT)
        g_HB[i] = __float2bfloat16(0.f);
    for (int i = gtid; i < 2 * 512 * 256; i += NT) g_C[i] = 0.f;
    for (int i = gtid; i < 2048; i += NT) {
        g_bias[i]        = bih0[i] + bhh0[i];
        g_bias[2048 + i] = bih1[i] + bhh1[i];
    }

    grid_barrier();

    // ======== merged mainloop: phase t = { L1(t-1), L0(t) } ========
    const int m_cta = blockIdx.x >> 2;
    const int n_cta = blockIdx.x & 3;
    const int grp = wid >> 2;              // K-half group
    const int wl  = wid & 3;
    const int wm  = wl >> 1;
    const int wn  = wl & 1;
    const int mt0 = m_cta * 4 + wm * 2;
    const int n8b = n_cta * 8 + wn * 4;

    const uint4* WP0v = (const uint4*)g_WP0;
    const uint4* WP1v = (const uint4*)g_WP1;
    const uint4* XPv  = (const uint4*)g_XP;
    const uint4* HBv  = (const uint4*)g_HB;
    float* gout0 = gsm + grp * 4096;          // L1(t-1) partials
    float* gout1 = gsm + 8192 + grp * 4096;   // L0(t)   partials

    for (int t = 0; t <= 512; t++) {
        const int u = t & 1, v = u ^ 1;
        const bool do1 = (t >= 1);     // L1(t-1) part
        const bool do0 = (t <= 511);   // L0(t)   part

        if (do1) {
            // L1(t-1): h0(t-1) @ lay0/parity v,  h1(t-2) @ lay1/parity u
            float acc[2][4][4] = {};
            const uint4* A0 = WP1v + (mt0 * NQ1) * 64 + lane * 2;
            const uint4* A1 = WP1v + ((mt0 + 1) * NQ1) * 64 + lane * 2;
            if (grp == 0) {
                gemm_seg<32>(A0, A1,
                             HBv + ((v * 2 + 0) * 1024 + n8b) * 32 + lane, acc);
            } else {
                gemm_seg<32>(A0 + 32 * 64, A1 + 32 * 64,
                             HBv + ((u * 2 + 1) * 1024 + n8b) * 32 + lane, acc);
            }
            store_partials(acc, gout0, wm, wn, lane);
        }
        if (do0) {
            // L0(t): h0(t-1) @ lay0/parity v,  x(t)
            float acc[2][4][4] = {};
            const uint4* A0 = WP0v + (mt0 * NQ0) * 64 + lane * 2;
            const uint4* A1 = WP0v + ((mt0 + 1) * NQ0) * 64 + lane * 2;
            const uint4* Bh = HBv + ((v * 2 + 0) * 1024 + n8b) * 32 + lane;
            if (grp == 0) {
                gemm_seg<18>(A0, A1, Bh, acc);
            } else {
                gemm_seg<14>(A0 + 18 * 64, A1 + 18 * 64, Bh + 18 * 1024, acc);
                gemm_seg<4>(A0 + 32 * 64, A1 + 32 * 64,
                            XPv + (t * 4 * 32 + n8b) * 32 + lane, acc);
            }
            store_partials(acc, gout1, wm, wn, lane);
        }
        __syncthreads();

        // combined cell-update tail
        if (do1) cell_upd(gsm,        1, v, m_cta, n_cta, tid, t == 512);
        if (do0) cell_upd(gsm + 8192, 0, u, m_cta, n_cta, tid, false);

        grid_barrier();
    }

    // ======== head ========
    if (blockIdx.x == 0) {
        int b = tid;
        float a = __ldg(bout);
#pragma unroll 8
        for (int j = 0; j < 512; j++)
            a += fmaxf(__ldcg(g_h1fin + j * 256 + b), 0.f) * __ldg(Wout + j);
        out[b] = a;
    }
}

// ---------------- launch ----------------------------------------------------
extern "C" void kernel_launch(void* const* d_in, const int* in_sizes, int n_in,
                              void* d_out, int out_size) {
    (void)in_sizes; (void)n_in; (void)out_size;
    const float* x    = (const float*)d_in[0];
    const float* Wih0 = (const float*)d_in[1];
    const float* Whh0 = (const float*)d_in[2];
    const float* bih0 = (const float*)d_in[3];
    const float* bhh0 = (const float*)d_in[4];
    const float* Wih1 = (const float*)d_in[5];
    const float* Whh1 = (const float*)d_in[6];
    const float* bih1 = (const float*)d_in[7];
    const float* bhh1 = (const float*)d_in[8];
    const float* Wout = (const float*)d_in[9];
    const float* bout = (const float*)d_in[10];
    float* out = (float*)d_out;

    cudaFuncSetAttribute(lstm_all, cudaFuncAttributeMaxDynamicSharedMemorySize, SMEM_DYN);
    lstm_all<<<NCTA, NTHR, SMEM_DYN>>>(x, Wih0, Whh0, bih0, bhh0,
                                       Wih1, Whh1, bih1, bhh1, Wout, bout, out);
}